// round 11
// baseline (speedup 1.0000x reference)
#include <cuda_runtime.h>
#include <cuda_fp16.h>

#define NN 100000
#define NE 1600000
#define DIN 128
#define HID 64
#define NG 512
#define NC 10

#define GEMM1_BLKS ((NN + 63) / 64)          // 1563
#define DEG4_BLKS  ((NE / 4 + 255) / 256)    // 1563
#define GCNT4_BLKS ((NN / 4 + 255) / 256)    // 98
#define PREP_BLKS  ((DIN * HID + HID * HID + 255) / 256)  // 48
#define SCAT_BLKS  ((NE + 255) / 256)        // 6250
#define SCAN_BLKS  ((NN + 1023) / 1024)      // 98

// ---------------- scratch (device globals; no allocation allowed) ----------
__device__ __align__(16) __half g_h[NN * HID];    // layer-1 features
__device__ __align__(16) __half g_h2[NN * HID];   // layer-2 features
__device__ __align__(16) __half g_W1t[HID * DIN]; // W1^T fp16 [n][k]
__device__ __align__(16) __half g_W2t[HID * HID]; // W2^T fp16 [n][k]
__device__ __align__(16) float g_pool[NG * HID];
__device__ float g_dinv[NN];
__device__ int   g_degi[NN];
__device__ int   g_ptr[NN + 1];
__device__ int   g_pos[NN];
__device__ int   g_gcnt[NG];
__device__ int   g_bsum[SCAN_BLKS];
__device__ int   g_boff[SCAN_BLKS];
__device__ int   g_scnt;
__device__ __align__(16) int2 g_edge[NE];    // {src, float_bits(coef)}

union HPack { uint2 u; __half2 h[2]; };

// ---------------- HMMA helper ----------------------------------------------
__device__ __forceinline__ void mma16816(float* c, unsigned a0, unsigned a1,
                                         unsigned a2, unsigned a3,
                                         unsigned b0, unsigned b1) {
    asm volatile(
        "mma.sync.aligned.m16n8k16.row.col.f32.f16.f16.f32 "
        "{%0,%1,%2,%3}, {%4,%5,%6,%7}, {%8,%9}, {%0,%1,%2,%3};"
        : "+f"(c[0]), "+f"(c[1]), "+f"(c[2]), "+f"(c[3])
        : "r"(a0), "r"(a1), "r"(a2), "r"(a3), "r"(b0), "r"(b1));
}

// ---------------- k_hist: degree | graph histogram | weight prep -----------
__global__ void k_hist(const int* __restrict__ ei, const int* __restrict__ batch,
                       const float* __restrict__ W1, const float* __restrict__ W2) {
    int b = blockIdx.x;
    if (b < DEG4_BLKS) {
        int q = b * 256 + threadIdx.x;
        if (q < NE / 4) {
            int4 d4 = __ldg((const int4*)(ei + NE) + q);
            atomicAdd(&g_degi[d4.x], 1);
            atomicAdd(&g_degi[d4.y], 1);
            atomicAdd(&g_degi[d4.z], 1);
            atomicAdd(&g_degi[d4.w], 1);
        }
    } else if (b < DEG4_BLKS + GCNT4_BLKS) {
        int q = (b - DEG4_BLKS) * 256 + threadIdx.x;
        if (q < NN / 4) {
            int4 b4 = __ldg((const int4*)batch + q);
            atomicAdd(&g_gcnt[b4.x], 1);
            atomicAdd(&g_gcnt[b4.y], 1);
            atomicAdd(&g_gcnt[b4.z], 1);
            atomicAdd(&g_gcnt[b4.w], 1);
        }
    } else {
        int t = (b - DEG4_BLKS - GCNT4_BLKS) * 256 + threadIdx.x;
        if (t < DIN * HID) {
            int k = t >> 6, n = t & 63;
            g_W1t[n * DIN + k] = __float2half(W1[t]);
        } else if (t < DIN * HID + HID * HID) {
            int q = t - DIN * HID;
            int k = q >> 6, n = q & 63;
            g_W2t[n * HID + k] = __float2half(W2[q]);
        }
    }
}

// ---------------- scan phases 1+2 fused (last-block scans partials) --------
__global__ void k_scan12() {
    __shared__ int wsum[32];
    __shared__ int isLast;
    int b = blockIdx.x, t = threadIdx.x;
    int idx = b * 1024 + t;
    int d = (idx < NN) ? g_degi[idx] : 0;
    int v = d;
#pragma unroll
    for (int o = 16; o > 0; o >>= 1) v += __shfl_down_sync(0xffffffffu, v, o);
    if ((t & 31) == 0) wsum[t >> 5] = v;
    __syncthreads();
    if (t < 32) {
        int s = wsum[t];
#pragma unroll
        for (int o = 16; o > 0; o >>= 1) s += __shfl_down_sync(0xffffffffu, s, o);
        if (t == 0) {
            g_bsum[b] = s;
            __threadfence();
            int c = atomicAdd(&g_scnt, 1);
            isLast = (c == SCAN_BLKS - 1);
        }
    }
    __syncthreads();
    if (isLast && t < 128) {
        __shared__ int ws[4];
        int lane = t & 31, w = t >> 5;
        int orig = (t < SCAN_BLKS) ? ((volatile int*)g_bsum)[t] : 0;
        int v2 = orig;
#pragma unroll
        for (int o = 1; o < 32; o <<= 1) {
            int u = __shfl_up_sync(0xffffffffu, v2, o);
            if (lane >= o) v2 += u;
        }
        if (lane == 31) ws[w] = v2;
        __syncwarp();
        __threadfence_block();
        // all 4 warps need ws; cheap spin-free: barrier over first 128 threads
        asm volatile("bar.sync 1, 128;" ::: "memory");
        int add = 0;
#pragma unroll
        for (int k = 0; k < 4; k++) add += (k < w) ? ws[k] : 0;
        if (t < SCAN_BLKS) g_boff[t] = v2 + add - orig;
    }
}

__global__ void k_scan3() {
    __shared__ int sd[1024];
    int b = blockIdx.x, t = threadIdx.x;
    int idx = b * 1024 + t;
    int d = (idx < NN) ? g_degi[idx] : 0;
    sd[t] = d;
    __syncthreads();
    for (int off = 1; off < 1024; off <<= 1) {
        int v = (t >= off) ? sd[t - off] : 0;
        __syncthreads();
        sd[t] += v;
        __syncthreads();
    }
    if (idx < NN) {
        int excl = sd[t] - d + g_boff[b];
        g_ptr[idx] = excl;
        g_pos[idx] = excl;
        g_dinv[idx] = rsqrtf((float)d + 1.0f);
    }
    if (b == SCAN_BLKS - 1 && t == 0) g_ptr[NN] = NE;
}

// ---------------- gemm1 via HMMA: Y = fp16(X @ W1) -------------------------
__device__ __forceinline__ void gemm1_mma(const float* __restrict__ X,
                                          __half* __restrict__ Y, int blk) {
    const int XS = 136;
    __shared__ __align__(16) __half Xs[64 * XS];
    __shared__ __align__(16) __half Ws[64 * XS];
    int t = threadIdx.x;
    int node0 = blk * 64;
#pragma unroll
    for (int i = 0; i < 8; i++) {
        int idx = t + i * 256;
        int row = idx >> 5, c4 = idx & 31;
        int node = node0 + row;
        if (node >= NN) node = NN - 1;
        float4 v = __ldg((const float4*)&X[(size_t)node * DIN + c4 * 4]);
        HPack pk;
        pk.h[0] = __floats2half2_rn(v.x, v.y);
        pk.h[1] = __floats2half2_rn(v.z, v.w);
        *(uint2*)&Xs[row * XS + c4 * 4] = pk.u;
    }
#pragma unroll
    for (int i = 0; i < 4; i++) {
        int idx = t + i * 256;
        int row = idx >> 4, c = idx & 15;
        ((float4*)Ws)[row * 17 + c] = ((const float4*)g_W1t)[row * 16 + c];
    }
    __syncthreads();

    int warp = t >> 5, lane = t & 31;
    int g = lane >> 2, tq = lane & 3;
    int mrow = (warp >> 1) * 16, ncol = (warp & 1) * 32;
    float acc[4][4];
#pragma unroll
    for (int j = 0; j < 4; j++)
#pragma unroll
        for (int c = 0; c < 4; c++) acc[j][c] = 0.f;

#pragma unroll
    for (int k0 = 0; k0 < DIN / 16; k0++) {
        int kb = k0 * 16 + 2 * tq;
        unsigned a0 = *(const unsigned*)&Xs[(mrow + g) * XS + kb];
        unsigned a1 = *(const unsigned*)&Xs[(mrow + g + 8) * XS + kb];
        unsigned a2 = *(const unsigned*)&Xs[(mrow + g) * XS + kb + 8];
        unsigned a3 = *(const unsigned*)&Xs[(mrow + g + 8) * XS + kb + 8];
#pragma unroll
        for (int j = 0; j < 4; j++) {
            int n = ncol + j * 8 + g;
            unsigned b0 = *(const unsigned*)&Ws[n * XS + kb];
            unsigned b1 = *(const unsigned*)&Ws[n * XS + kb + 8];
            mma16816(acc[j], a0, a1, a2, a3, b0, b1);
        }
    }
#pragma unroll
    for (int j = 0; j < 4; j++) {
        int col = ncol + j * 8 + 2 * tq;
        int n1 = node0 + mrow + g, n2 = n1 + 8;
        if (n1 < NN) {
            __half2 p = __floats2half2_rn(acc[j][0], acc[j][1]);
            *(__half2*)&Y[(size_t)n1 * HID + col] = p;
        }
        if (n2 < NN) {
            __half2 p = __floats2half2_rn(acc[j][2], acc[j][3]);
            *(__half2*)&Y[(size_t)n2 * HID + col] = p;
        }
    }
}

// ---------------- k_work: gemm1 | edge scatter (independent, co-scheduled) -
__global__ void k_work(const float* __restrict__ x, const int* __restrict__ ei,
                       __half* __restrict__ Y) {
    int b = blockIdx.x;
    if (b < GEMM1_BLKS) {
        gemm1_mma(x, Y, b);
    } else {
        int e = (b - GEMM1_BLKS) * 256 + threadIdx.x;
        if (e < NE) {
            int src = __ldg(&ei[e]);
            int dst = __ldg(&ei[NE + e]);
            int p = atomicAdd(&g_pos[dst], 1);
            float cf = __ldg(&g_dinv[src]) * __ldg(&g_dinv[dst]);
            g_edge[p] = make_int2(src, __float_as_int(cf));
        }
    }
}

// ---------------- node aggregation core (warp-collective, 4x unroll) -------
__device__ __forceinline__ float4 agg_node(const __half* __restrict__ H,
                                           int node, int j, int sub,
                                           const float* __restrict__ bias) {
    int start = __ldg(&g_ptr[node]);
    int end   = __ldg(&g_ptr[node + 1]);
    const uint2* h2 = (const uint2*)H;
    float4 a0 = make_float4(0.f, 0.f, 0.f, 0.f);
    float4 a1 = make_float4(0.f, 0.f, 0.f, 0.f);
    float4 a2 = make_float4(0.f, 0.f, 0.f, 0.f);
    float4 a3 = make_float4(0.f, 0.f, 0.f, 0.f);
    int p = start + sub;
    for (; p + 6 < end; p += 8) {
        int2 e0 = __ldg(&g_edge[p]);
        int2 e1 = __ldg(&g_edge[p + 2]);
        int2 e2 = __ldg(&g_edge[p + 4]);
        int2 e3 = __ldg(&g_edge[p + 6]);
        HPack v0, v1, v2, v3;
        v0.u = __ldg(h2 + (size_t)e0.x * 16 + j);
        v1.u = __ldg(h2 + (size_t)e1.x * 16 + j);
        v2.u = __ldg(h2 + (size_t)e2.x * 16 + j);
        v3.u = __ldg(h2 + (size_t)e3.x * 16 + j);
        float c0 = __int_as_float(e0.y), c1 = __int_as_float(e1.y);
        float c2 = __int_as_float(e2.y), c3 = __int_as_float(e3.y);
        float2 fa, fb;
        fa = __half22float2(v0.h[0]); fb = __half22float2(v0.h[1]);
        a0.x += fa.x * c0; a0.y += fa.y * c0; a0.z += fb.x * c0; a0.w += fb.y * c0;
        fa = __half22float2(v1.h[0]); fb = __half22float2(v1.h[1]);
        a1.x += fa.x * c1; a1.y += fa.y * c1; a1.z += fb.x * c1; a1.w += fb.y * c1;
        fa = __half22float2(v2.h[0]); fb = __half22float2(v2.h[1]);
        a2.x += fa.x * c2; a2.y += fa.y * c2; a2.z += fb.x * c2; a2.w += fb.y * c2;
        fa = __half22float2(v3.h[0]); fb = __half22float2(v3.h[1]);
        a3.x += fa.x * c3; a3.y += fa.y * c3; a3.z += fb.x * c3; a3.w += fb.y * c3;
    }
    for (; p < end; p += 2) {
        int2 e0 = __ldg(&g_edge[p]);
        float c0 = __int_as_float(e0.y);
        HPack v0;
        v0.u = __ldg(h2 + (size_t)e0.x * 16 + j);
        float2 fa = __half22float2(v0.h[0]), fb = __half22float2(v0.h[1]);
        a0.x += fa.x * c0; a0.y += fa.y * c0; a0.z += fb.x * c0; a0.w += fb.y * c0;
    }
    a0.x += a1.x + a2.x + a3.x;
    a0.y += a1.y + a2.y + a3.y;
    a0.z += a1.z + a2.z + a3.z;
    a0.w += a1.w + a2.w + a3.w;
    a0.x += __shfl_down_sync(0xffffffffu, a0.x, 16);
    a0.y += __shfl_down_sync(0xffffffffu, a0.y, 16);
    a0.z += __shfl_down_sync(0xffffffffu, a0.z, 16);
    a0.w += __shfl_down_sync(0xffffffffu, a0.w, 16);
    float4 r = make_float4(0.f, 0.f, 0.f, 0.f);
    if (sub == 0) {
        float dn = __ldg(&g_dinv[node]);
        float c = dn * dn;
        HPack hs;
        hs.u = __ldg((const uint2*)H + (size_t)node * 16 + j);
        float2 ha = __half22float2(hs.h[0]), hb = __half22float2(hs.h[1]);
        float4 b = __ldg((const float4*)bias + j);
        r.x = fmaxf(a0.x + ha.x * c + b.x, 0.f);
        r.y = fmaxf(a0.y + ha.y * c + b.y, 0.f);
        r.z = fmaxf(a0.z + hb.x * c + b.z, 0.f);
        r.w = fmaxf(a0.w + hb.y * c + b.w, 0.f);
    }
    return r;
}

// ---------------- fused agg1 + gemm2(HMMA): reads g_h, writes g_h2 ---------
__global__ void k_mid(const float* __restrict__ bias, __half* __restrict__ Y) {
    const int AS = 72;
    __shared__ __align__(16) __half As[64 * AS];
    __shared__ __align__(16) __half W2s[64 * AS];
    int t = threadIdx.x;
    int warp = t >> 5, lane = t & 31;
    int j = lane & 15, sub = lane >> 4;
    int node0 = blockIdx.x * 64;

#pragma unroll
    for (int i = 0; i < 2; i++) {
        int idx = t + i * 256;
        int row = idx >> 3, c = idx & 7;
        ((float4*)W2s)[row * 9 + c] = ((const float4*)g_W2t)[row * 8 + c];
    }

#pragma unroll 1
    for (int s = 0; s < 8; s++) {
        int row = warp * 8 + s;
        int node = node0 + row;
        float4 r = make_float4(0.f, 0.f, 0.f, 0.f);
        if (node < NN) r = agg_node(g_h, node, j, sub, bias);
        if (sub == 0) {
            HPack pk;
            pk.h[0] = __floats2half2_rn(r.x, r.y);
            pk.h[1] = __floats2half2_rn(r.z, r.w);
            *(uint2*)&As[row * AS + 4 * j] = pk.u;
        }
    }
    __syncthreads();

    int g = lane >> 2, tq = lane & 3;
    int mrow = (warp >> 1) * 16, ncol = (warp & 1) * 32;
    float acc[4][4];
#pragma unroll
    for (int jj = 0; jj < 4; jj++)
#pragma unroll
        for (int c = 0; c < 4; c++) acc[jj][c] = 0.f;

#pragma unroll
    for (int k0 = 0; k0 < HID / 16; k0++) {
        int kb = k0 * 16 + 2 * tq;
        unsigned a0 = *(const unsigned*)&As[(mrow + g) * AS + kb];
        unsigned a1 = *(const unsigned*)&As[(mrow + g + 8) * AS + kb];
        unsigned a2 = *(const unsigned*)&As[(mrow + g) * AS + kb + 8];
        unsigned a3 = *(const unsigned*)&As[(mrow + g + 8) * AS + kb + 8];
#pragma unroll
        for (int jj = 0; jj < 4; jj++) {
            int n = ncol + jj * 8 + g;
            unsigned b0 = *(const unsigned*)&W2s[n * AS + kb];
            unsigned b1 = *(const unsigned*)&W2s[n * AS + kb + 8];
            mma16816(acc[jj], a0, a1, a2, a3, b0, b1);
        }
    }
#pragma unroll
    for (int jj = 0; jj < 4; jj++) {
        int col = ncol + jj * 8 + 2 * tq;
        int n1 = node0 + mrow + g, n2 = n1 + 8;
        if (n1 < NN) {
            __half2 p = __floats2half2_rn(acc[jj][0], acc[jj][1]);
            *(__half2*)&Y[(size_t)n1 * HID + col] = p;
        }
        if (n2 < NN) {
            __half2 p = __floats2half2_rn(acc[jj][2], acc[jj][3]);
            *(__half2*)&Y[(size_t)n2 * HID + col] = p;
        }
    }
}

// ---------------- layer-2 aggregation + fused pool (reads g_h2) ------------
__global__ void k_aggpool(const float* __restrict__ bias,
                          const int* __restrict__ batch) {
    int warp = threadIdx.x >> 5, lane = threadIdx.x & 31;
    int j = lane & 15, sub = lane >> 4;
    int node = blockIdx.x * 8 + warp;
    if (node >= NN) return;
    float4 r = agg_node(g_h2, node, j, sub, bias);
    if (sub == 0) {
        int g = __ldg(&batch[node]);
        float4* p4 = (float4*)g_pool + (size_t)g * 16 + j;
        asm volatile("red.global.add.v4.f32 [%0], {%1, %2, %3, %4};"
                     :: "l"(p4), "f"(r.x), "f"(r.y), "f"(r.z), "f"(r.w)
                     : "memory");
    }
}

// ---------------- head -----------------------------------------------------
__global__ void k_head(const float* __restrict__ Wfc, const float* __restrict__ bfc,
                       float* __restrict__ out) {
    __shared__ float Wf[HID * NC];
    __shared__ float bf[NC];
    for (int i = threadIdx.x; i < HID * NC; i += blockDim.x) Wf[i] = Wfc[i];
    if (threadIdx.x < NC) bf[threadIdx.x] = bfc[threadIdx.x];
    __syncthreads();
    int g = blockIdx.x * blockDim.x + threadIdx.x;
    if (g >= NG) return;
    float inv = 1.0f / fmaxf((float)g_gcnt[g], 1.0f);
    float l[NC];
#pragma unroll
    for (int j = 0; j < NC; j++) l[j] = bf[j];
    for (int k = 0; k < HID; k++) {
        float pv = g_pool[g * HID + k] * inv;
#pragma unroll
        for (int j = 0; j < NC; j++) l[j] += pv * Wf[k * NC + j];
    }
    float m = l[0];
#pragma unroll
    for (int j = 1; j < NC; j++) m = fmaxf(m, l[j]);
    float s = 0.f;
#pragma unroll
    for (int j = 0; j < NC; j++) s += expf(l[j] - m);
    float lse = m + logf(s);
#pragma unroll
    for (int j = 0; j < NC; j++) out[g * NC + j] = l[j] - lse;
}

// ---------------------------------------------------------------------------
extern "C" void kernel_launch(void* const* d_in, const int* in_sizes, int n_in,
                              void* d_out, int out_size) {
    const float* x     = (const float*)d_in[0];
    const int*   ei    = (const int*)d_in[1];
    const int*   batch = (const int*)d_in[2];
    const float* W1    = (const float*)d_in[3];
    const float* b1    = (const float*)d_in[4];
    const float* W2    = (const float*)d_in[5];
    const float* b2    = (const float*)d_in[6];
    const float* Wfc   = (const float*)d_in[7];
    const float* bfc   = (const float*)d_in[8];
    float* out = (float*)d_out;

    // Resolve REAL device addresses (host shadow symbols are a silent ATS trap).
    void *p_degi, *p_gcnt, *p_pool, *p_h, *p_h2, *p_scnt;
    cudaGetSymbolAddress(&p_degi, g_degi);
    cudaGetSymbolAddress(&p_gcnt, g_gcnt);
    cudaGetSymbolAddress(&p_pool, g_pool);
    cudaGetSymbolAddress(&p_h,    g_h);
    cudaGetSymbolAddress(&p_h2,   g_h2);
    cudaGetSymbolAddress(&p_scnt, g_scnt);
    __half* dh  = (__half*)p_h;
    __half* dh2 = (__half*)p_h2;

    cudaMemsetAsync(p_degi, 0, NN * sizeof(int));
    cudaMemsetAsync(p_gcnt, 0, NG * sizeof(int));
    cudaMemsetAsync(p_pool, 0, NG * HID * sizeof(float));
    cudaMemsetAsync(p_scnt, 0, sizeof(int));

    // histograms + weight prep (all independent)
    k_hist<<<DEG4_BLKS + GCNT4_BLKS + PREP_BLKS, 256>>>(ei, batch, W1, W2);

    // CSR pointers (scan12 fused via last-block trick)
    k_scan12<<<SCAN_BLKS, 1024>>>();
    k_scan3<<<SCAN_BLKS, 1024>>>();

    // gemm1 (HMMA) co-scheduled with edge scatter — independent work
    k_work<<<GEMM1_BLKS + SCAT_BLKS, 256>>>(x, ei, dh);

    // fused agg1 + gemm2(HMMA): reads g_h, writes g_h2
    k_mid<<<(NN + 63) / 64, 256>>>(b1, dh2);

    // layer-2 aggregation + fused pool (reads g_h2)
    k_aggpool<<<(NN + 7) / 8, 256>>>(b2, batch);

    // head
    k_head<<<1, NG>>>(Wfc, bfc, out);
}

// round 12
// speedup vs baseline: 1.2727x; 1.2727x over previous
#include <cuda_runtime.h>
#include <cuda_fp16.h>

#define NN 100000
#define NE 1600000
#define DIN 128
#define HID 64
#define NG 512
#define NC 10

#define GEMM1_BLKS ((NN + 63) / 64)          // 1563
#define DEG4_BLKS  ((NE / 4 + 255) / 256)    // 1563
#define GCNT4_BLKS ((NN / 4 + 255) / 256)    // 98
#define SCAN_BLKS  ((NN + 1023) / 1024)      // 98

// ---------------- scratch (device globals; no allocation allowed) ----------
__device__ __align__(16) __half g_h[NN * HID];    // layer-1 features
__device__ __align__(16) __half g_h2[NN * HID];   // layer-2 features
__device__ __align__(16) __half g_W1t[HID * DIN]; // W1^T fp16 [n][k]
__device__ __align__(16) __half g_W2t[HID * HID]; // W2^T fp16 [n][k]
__device__ __align__(16) float g_pool[NG * HID];
__device__ float g_dinv[NN];
__device__ int   g_degi[NN];
__device__ int   g_ptr[NN + 1];
__device__ int   g_pos[NN];
__device__ int   g_gcnt[NG];
__device__ int   g_bsum[SCAN_BLKS];
__device__ int   g_boff[SCAN_BLKS];
__device__ int   g_scnt;
__device__ __align__(16) int2 g_edge[NE];    // {src, float_bits(coef)}

union HPack { uint2 u; __half2 h[2]; };

// ---------------- HMMA helper ----------------------------------------------
__device__ __forceinline__ void mma16816(float* c, unsigned a0, unsigned a1,
                                         unsigned a2, unsigned a3,
                                         unsigned b0, unsigned b1) {
    asm volatile(
        "mma.sync.aligned.m16n8k16.row.col.f32.f16.f16.f32 "
        "{%0,%1,%2,%3}, {%4,%5,%6,%7}, {%8,%9}, {%0,%1,%2,%3};"
        : "+f"(c[0]), "+f"(c[1]), "+f"(c[2]), "+f"(c[3])
        : "r"(a0), "r"(a1), "r"(a2), "r"(a3), "r"(b0), "r"(b1));
}

// ---------------- prep: transpose weights to fp16 [n][k] -------------------
__global__ void k_prep(const float* __restrict__ W1, const float* __restrict__ W2) {
    int t = blockIdx.x * 256 + threadIdx.x;
    if (t < DIN * HID) {
        int k = t >> 6, n = t & 63;
        g_W1t[n * DIN + k] = __float2half(W1[t]);
    } else if (t < DIN * HID + HID * HID) {
        int q = t - DIN * HID;
        int k = q >> 6, n = q & 63;
        g_W2t[n * HID + k] = __float2half(W2[q]);
    }
}

// ---------------- gemm1 via HMMA: Y = fp16(X @ W1) -------------------------
__device__ __forceinline__ void gemm1_mma(const float* __restrict__ X,
                                          __half* __restrict__ Y, int blk) {
    const int XS = 136;
    __shared__ __align__(16) __half Xs[64 * XS];
    __shared__ __align__(16) __half Ws[64 * XS];
    int t = threadIdx.x;
    int node0 = blk * 64;
#pragma unroll
    for (int i = 0; i < 8; i++) {
        int idx = t + i * 256;
        int row = idx >> 5, c4 = idx & 31;
        int node = node0 + row;
        if (node >= NN) node = NN - 1;
        float4 v = __ldg((const float4*)&X[(size_t)node * DIN + c4 * 4]);
        HPack pk;
        pk.h[0] = __floats2half2_rn(v.x, v.y);
        pk.h[1] = __floats2half2_rn(v.z, v.w);
        *(uint2*)&Xs[row * XS + c4 * 4] = pk.u;
    }
#pragma unroll
    for (int i = 0; i < 4; i++) {
        int idx = t + i * 256;
        int row = idx >> 4, c = idx & 15;
        ((float4*)Ws)[row * 17 + c] = ((const float4*)g_W1t)[row * 16 + c];
    }
    __syncthreads();

    int warp = t >> 5, lane = t & 31;
    int g = lane >> 2, tq = lane & 3;
    int mrow = (warp >> 1) * 16, ncol = (warp & 1) * 32;
    float acc[4][4];
#pragma unroll
    for (int j = 0; j < 4; j++)
#pragma unroll
        for (int c = 0; c < 4; c++) acc[j][c] = 0.f;

#pragma unroll
    for (int k0 = 0; k0 < DIN / 16; k0++) {
        int kb = k0 * 16 + 2 * tq;
        unsigned a0 = *(const unsigned*)&Xs[(mrow + g) * XS + kb];
        unsigned a1 = *(const unsigned*)&Xs[(mrow + g + 8) * XS + kb];
        unsigned a2 = *(const unsigned*)&Xs[(mrow + g) * XS + kb + 8];
        unsigned a3 = *(const unsigned*)&Xs[(mrow + g + 8) * XS + kb + 8];
#pragma unroll
        for (int j = 0; j < 4; j++) {
            int n = ncol + j * 8 + g;
            unsigned b0 = *(const unsigned*)&Ws[n * XS + kb];
            unsigned b1 = *(const unsigned*)&Ws[n * XS + kb + 8];
            mma16816(acc[j], a0, a1, a2, a3, b0, b1);
        }
    }
#pragma unroll
    for (int j = 0; j < 4; j++) {
        int col = ncol + j * 8 + 2 * tq;
        int n1 = node0 + mrow + g, n2 = n1 + 8;
        if (n1 < NN) {
            __half2 p = __floats2half2_rn(acc[j][0], acc[j][1]);
            *(__half2*)&Y[(size_t)n1 * HID + col] = p;
        }
        if (n2 < NN) {
            __half2 p = __floats2half2_rn(acc[j][2], acc[j][3]);
            *(__half2*)&Y[(size_t)n2 * HID + col] = p;
        }
    }
}

// ---------------- fused front: gemm1 | degree histogram | graph histogram --
__global__ void k_front(const float* __restrict__ x,
                        const int* __restrict__ ei, const int* __restrict__ batch,
                        __half* __restrict__ Y) {
    int b = blockIdx.x;
    if (b < GEMM1_BLKS) {
        gemm1_mma(x, Y, b);
    } else if (b < GEMM1_BLKS + DEG4_BLKS) {
        int q = (b - GEMM1_BLKS) * 256 + threadIdx.x;
        if (q < NE / 4) {
            int4 d4 = __ldg((const int4*)(ei + NE) + q);
            atomicAdd(&g_degi[d4.x], 1);
            atomicAdd(&g_degi[d4.y], 1);
            atomicAdd(&g_degi[d4.z], 1);
            atomicAdd(&g_degi[d4.w], 1);
        }
    } else {
        int q = (b - GEMM1_BLKS - DEG4_BLKS) * 256 + threadIdx.x;
        if (q < NN / 4) {
            int4 b4 = __ldg((const int4*)batch + q);
            atomicAdd(&g_gcnt[b4.x], 1);
            atomicAdd(&g_gcnt[b4.y], 1);
            atomicAdd(&g_gcnt[b4.z], 1);
            atomicAdd(&g_gcnt[b4.w], 1);
        }
    }
}

// ---------------- scan phases 1+2 fused (last-block scans partials) --------
__global__ void k_scan12() {
    __shared__ int wsum[32];
    __shared__ int isLast;
    int b = blockIdx.x, t = threadIdx.x;
    int idx = b * 1024 + t;
    int d = (idx < NN) ? g_degi[idx] : 0;
    int v = d;
#pragma unroll
    for (int o = 16; o > 0; o >>= 1) v += __shfl_down_sync(0xffffffffu, v, o);
    if ((t & 31) == 0) wsum[t >> 5] = v;
    __syncthreads();
    if (t < 32) {
        int s = wsum[t];
#pragma unroll
        for (int o = 16; o > 0; o >>= 1) s += __shfl_down_sync(0xffffffffu, s, o);
        if (t == 0) {
            g_bsum[b] = s;
            __threadfence();
            int c = atomicAdd(&g_scnt, 1);
            isLast = (c == SCAN_BLKS - 1);
        }
    }
    __syncthreads();
    if (isLast && t < 128) {
        __shared__ int ws[4];
        int lane = t & 31, w = t >> 5;
        int orig = (t < SCAN_BLKS) ? ((volatile int*)g_bsum)[t] : 0;
        int v2 = orig;
#pragma unroll
        for (int o = 1; o < 32; o <<= 1) {
            int u = __shfl_up_sync(0xffffffffu, v2, o);
            if (lane >= o) v2 += u;
        }
        if (lane == 31) ws[w] = v2;
        asm volatile("bar.sync 1, 128;" ::: "memory");
        int add = 0;
#pragma unroll
        for (int k = 0; k < 4; k++) add += (k < w) ? ws[k] : 0;
        if (t < SCAN_BLKS) g_boff[t] = v2 + add - orig;
    }
}

__global__ void k_scan3() {
    __shared__ int sd[1024];
    int b = blockIdx.x, t = threadIdx.x;
    int idx = b * 1024 + t;
    int d = (idx < NN) ? g_degi[idx] : 0;
    sd[t] = d;
    __syncthreads();
    for (int off = 1; off < 1024; off <<= 1) {
        int v = (t >= off) ? sd[t - off] : 0;
        __syncthreads();
        sd[t] += v;
        __syncthreads();
    }
    if (idx < NN) {
        int excl = sd[t] - d + g_boff[b];
        g_ptr[idx] = excl;
        g_pos[idx] = excl;
        g_dinv[idx] = rsqrtf((float)d + 1.0f);
    }
    if (b == SCAN_BLKS - 1 && t == 0) g_ptr[NN] = NE;
}

// ---------------- scatter: 2 edges per thread ------------------------------
__global__ void k_scatter(const int* __restrict__ ei) {
    int q = blockIdx.x * blockDim.x + threadIdx.x;
    if (q >= NE / 2) return;
    int2 s2 = __ldg((const int2*)ei + q);
    int2 d2 = __ldg((const int2*)(ei + NE) + q);
    int p0 = atomicAdd(&g_pos[d2.x], 1);
    int p1 = atomicAdd(&g_pos[d2.y], 1);
    float c0 = __ldg(&g_dinv[s2.x]) * __ldg(&g_dinv[d2.x]);
    float c1 = __ldg(&g_dinv[s2.y]) * __ldg(&g_dinv[d2.y]);
    g_edge[p0] = make_int2(s2.x, __float_as_int(c0));
    g_edge[p1] = make_int2(s2.y, __float_as_int(c1));
}

// ---------------- node aggregation core (warp-collective, 8x unroll) -------
__device__ __forceinline__ float4 agg_node(const __half* __restrict__ H,
                                           int node, int j, int sub,
                                           const float* __restrict__ bias) {
    int start = __ldg(&g_ptr[node]);
    int end   = __ldg(&g_ptr[node + 1]);
    const uint2* h2 = (const uint2*)H;
    float4 a0 = make_float4(0.f, 0.f, 0.f, 0.f);
    float4 a1 = make_float4(0.f, 0.f, 0.f, 0.f);
    int p = start + sub;
    // 8 edges in flight per 16-lane sub (16 per warp)
    for (; p + 14 < end; p += 16) {
        int2 e[8];
        HPack v[8];
#pragma unroll
        for (int u = 0; u < 8; u++) e[u] = __ldg(&g_edge[p + 2 * u]);
#pragma unroll
        for (int u = 0; u < 8; u++) v[u].u = __ldg(h2 + (size_t)e[u].x * 16 + j);
#pragma unroll
        for (int u = 0; u < 8; u++) {
            float c = __int_as_float(e[u].y);
            float2 fa = __half22float2(v[u].h[0]), fb = __half22float2(v[u].h[1]);
            if (u & 1) {
                a1.x += fa.x * c; a1.y += fa.y * c; a1.z += fb.x * c; a1.w += fb.y * c;
            } else {
                a0.x += fa.x * c; a0.y += fa.y * c; a0.z += fb.x * c; a0.w += fb.y * c;
            }
        }
    }
    for (; p < end; p += 2) {
        int2 e0 = __ldg(&g_edge[p]);
        float c0 = __int_as_float(e0.y);
        HPack v0;
        v0.u = __ldg(h2 + (size_t)e0.x * 16 + j);
        float2 fa = __half22float2(v0.h[0]), fb = __half22float2(v0.h[1]);
        a0.x += fa.x * c0; a0.y += fa.y * c0; a0.z += fb.x * c0; a0.w += fb.y * c0;
    }
    a0.x += a1.x; a0.y += a1.y; a0.z += a1.z; a0.w += a1.w;
    a0.x += __shfl_down_sync(0xffffffffu, a0.x, 16);
    a0.y += __shfl_down_sync(0xffffffffu, a0.y, 16);
    a0.z += __shfl_down_sync(0xffffffffu, a0.z, 16);
    a0.w += __shfl_down_sync(0xffffffffu, a0.w, 16);
    float4 r = make_float4(0.f, 0.f, 0.f, 0.f);
    if (sub == 0) {
        float dn = __ldg(&g_dinv[node]);
        float c = dn * dn;
        HPack hs;
        hs.u = __ldg((const uint2*)H + (size_t)node * 16 + j);
        float2 ha = __half22float2(hs.h[0]), hb = __half22float2(hs.h[1]);
        float4 b = __ldg((const float4*)bias + j);
        r.x = fmaxf(a0.x + ha.x * c + b.x, 0.f);
        r.y = fmaxf(a0.y + ha.y * c + b.y, 0.f);
        r.z = fmaxf(a0.z + hb.x * c + b.z, 0.f);
        r.w = fmaxf(a0.w + hb.y * c + b.w, 0.f);
    }
    return r;
}

// ---------------- fused agg1 + gemm2(HMMA): reads g_h, writes g_h2 ---------
__global__ void k_mid(const float* __restrict__ bias, __half* __restrict__ Y) {
    const int AS = 72;
    __shared__ __align__(16) __half As[64 * AS];
    __shared__ __align__(16) __half W2s[64 * AS];
    int t = threadIdx.x;
    int warp = t >> 5, lane = t & 31;
    int j = lane & 15, sub = lane >> 4;
    int node0 = blockIdx.x * 64;

#pragma unroll
    for (int i = 0; i < 2; i++) {
        int idx = t + i * 256;
        int row = idx >> 3, c = idx & 7;
        ((float4*)W2s)[row * 9 + c] = ((const float4*)g_W2t)[row * 8 + c];
    }

#pragma unroll 1
    for (int s = 0; s < 8; s++) {
        int row = warp * 8 + s;
        int node = node0 + row;
        float4 r = make_float4(0.f, 0.f, 0.f, 0.f);
        if (node < NN) r = agg_node(g_h, node, j, sub, bias);
        if (sub == 0) {
            HPack pk;
            pk.h[0] = __floats2half2_rn(r.x, r.y);
            pk.h[1] = __floats2half2_rn(r.z, r.w);
            *(uint2*)&As[row * AS + 4 * j] = pk.u;
        }
    }
    __syncthreads();

    int g = lane >> 2, tq = lane & 3;
    int mrow = (warp >> 1) * 16, ncol = (warp & 1) * 32;
    float acc[4][4];
#pragma unroll
    for (int jj = 0; jj < 4; jj++)
#pragma unroll
        for (int c = 0; c < 4; c++) acc[jj][c] = 0.f;

#pragma unroll
    for (int k0 = 0; k0 < HID / 16; k0++) {
        int kb = k0 * 16 + 2 * tq;
        unsigned a0 = *(const unsigned*)&As[(mrow + g) * AS + kb];
        unsigned a1 = *(const unsigned*)&As[(mrow + g + 8) * AS + kb];
        unsigned a2 = *(const unsigned*)&As[(mrow + g) * AS + kb + 8];
        unsigned a3 = *(const unsigned*)&As[(mrow + g + 8) * AS + kb + 8];
#pragma unroll
        for (int jj = 0; jj < 4; jj++) {
            int n = ncol + jj * 8 + g;
            unsigned b0 = *(const unsigned*)&W2s[n * AS + kb];
            unsigned b1 = *(const unsigned*)&W2s[n * AS + kb + 8];
            mma16816(acc[jj], a0, a1, a2, a3, b0, b1);
        }
    }
#pragma unroll
    for (int jj = 0; jj < 4; jj++) {
        int col = ncol + jj * 8 + 2 * tq;
        int n1 = node0 + mrow + g, n2 = n1 + 8;
        if (n1 < NN) {
            __half2 p = __floats2half2_rn(acc[jj][0], acc[jj][1]);
            *(__half2*)&Y[(size_t)n1 * HID + col] = p;
        }
        if (n2 < NN) {
            __half2 p = __floats2half2_rn(acc[jj][2], acc[jj][3]);
            *(__half2*)&Y[(size_t)n2 * HID + col] = p;
        }
    }
}

// ---------------- layer-2 aggregation + fused pool (reads g_h2) ------------
__global__ void k_aggpool(const float* __restrict__ bias,
                          const int* __restrict__ batch) {
    int warp = threadIdx.x >> 5, lane = threadIdx.x & 31;
    int j = lane & 15, sub = lane >> 4;
    int node = blockIdx.x * 8 + warp;
    if (node >= NN) return;
    float4 r = agg_node(g_h2, node, j, sub, bias);
    if (sub == 0) {
        int g = __ldg(&batch[node]);
        float4* p4 = (float4*)g_pool + (size_t)g * 16 + j;
        asm volatile("red.global.add.v4.f32 [%0], {%1, %2, %3, %4};"
                     :: "l"(p4), "f"(r.x), "f"(r.y), "f"(r.z), "f"(r.w)
                     : "memory");
    }
}

// ---------------- head -----------------------------------------------------
__global__ void k_head(const float* __restrict__ Wfc, const float* __restrict__ bfc,
                       float* __restrict__ out) {
    __shared__ float Wf[HID * NC];
    __shared__ float bf[NC];
    for (int i = threadIdx.x; i < HID * NC; i += blockDim.x) Wf[i] = Wfc[i];
    if (threadIdx.x < NC) bf[threadIdx.x] = bfc[threadIdx.x];
    __syncthreads();
    int g = blockIdx.x * blockDim.x + threadIdx.x;
    if (g >= NG) return;
    float inv = 1.0f / fmaxf((float)g_gcnt[g], 1.0f);
    float l[NC];
#pragma unroll
    for (int j = 0; j < NC; j++) l[j] = bf[j];
    for (int k = 0; k < HID; k++) {
        float pv = g_pool[g * HID + k] * inv;
#pragma unroll
        for (int j = 0; j < NC; j++) l[j] += pv * Wf[k * NC + j];
    }
    float m = l[0];
#pragma unroll
    for (int j = 1; j < NC; j++) m = fmaxf(m, l[j]);
    float s = 0.f;
#pragma unroll
    for (int j = 0; j < NC; j++) s += expf(l[j] - m);
    float lse = m + logf(s);
#pragma unroll
    for (int j = 0; j < NC; j++) out[g * NC + j] = l[j] - lse;
}

// ---------------------------------------------------------------------------
extern "C" void kernel_launch(void* const* d_in, const int* in_sizes, int n_in,
                              void* d_out, int out_size) {
    const float* x     = (const float*)d_in[0];
    const int*   ei    = (const int*)d_in[1];
    const int*   batch = (const int*)d_in[2];
    const float* W1    = (const float*)d_in[3];
    const float* b1    = (const float*)d_in[4];
    const float* W2    = (const float*)d_in[5];
    const float* b2    = (const float*)d_in[6];
    const float* Wfc   = (const float*)d_in[7];
    const float* bfc   = (const float*)d_in[8];
    float* out = (float*)d_out;

    // Resolve REAL device addresses (host shadow symbols are a silent ATS trap).
    void *p_degi, *p_gcnt, *p_pool, *p_h, *p_h2, *p_scnt;
    cudaGetSymbolAddress(&p_degi, g_degi);
    cudaGetSymbolAddress(&p_gcnt, g_gcnt);
    cudaGetSymbolAddress(&p_pool, g_pool);
    cudaGetSymbolAddress(&p_h,    g_h);
    cudaGetSymbolAddress(&p_h2,   g_h2);
    cudaGetSymbolAddress(&p_scnt, g_scnt);
    __half* dh  = (__half*)p_h;
    __half* dh2 = (__half*)p_h2;

    cudaMemsetAsync(p_degi, 0, NN * sizeof(int));
    cudaMemsetAsync(p_gcnt, 0, NG * sizeof(int));
    cudaMemsetAsync(p_pool, 0, NG * HID * sizeof(float));
    cudaMemsetAsync(p_scnt, 0, sizeof(int));

    // weight transpose/convert (tiny)
    k_prep<<<(DIN * HID + HID * HID + 255) / 256, 256>>>(W1, W2);

    // fused: gemm1(HMMA) + degree histogram + graph histogram (R9 structure)
    k_front<<<GEMM1_BLKS + DEG4_BLKS + GCNT4_BLKS, 256>>>(x, ei, batch, dh);

    // CSR pointers (scan1+2 fused) + packed edge scatter (2 edges/thread)
    k_scan12<<<SCAN_BLKS, 1024>>>();
    k_scan3<<<SCAN_BLKS, 1024>>>();
    k_scatter<<<(NE / 2 + 255) / 256, 256>>>(ei);

    // fused agg1 + gemm2(HMMA): reads g_h, writes g_h2
    k_mid<<<(NN + 63) / 64, 256>>>(b1, dh2);

    // layer-2 aggregation + fused pool (reads g_h2)
    k_aggpool<<<(NN + 7) / 8, 256>>>(b2, batch);

    // head
    k_head<<<1, NG>>>(Wfc, bfc, out);
}

// round 13
// speedup vs baseline: 1.3147x; 1.0330x over previous
#include <cuda_runtime.h>
#include <cuda_fp16.h>

#define NN 100000
#define NE 1600000
#define DIN 128
#define HID 64
#define NG 512
#define NC 10

#define GEMM1_BLKS ((NN + 63) / 64)          // 1563
#define DEG4_BLKS  ((NE / 4 + 255) / 256)    // 1563
#define GCNT4_BLKS ((NN / 4 + 255) / 256)    // 98
#define W2_BLKS    ((HID * HID + 255) / 256) // 16
#define SCAN_BLKS  ((NN + 1023) / 1024)      // 98

// ---------------- scratch (device globals; no allocation allowed) ----------
__device__ __align__(16) __half g_h[NN * HID];    // layer-1 features
__device__ __align__(16) __half g_h2[NN * HID];   // layer-2 features
__device__ __align__(16) __half g_W2t[HID * HID]; // W2^T fp16 [n][k]
__device__ __align__(16) float g_pool[NG * HID];
__device__ float g_dinv[NN];
__device__ int   g_degi[NN];
__device__ int   g_ptr[NN + 1];
__device__ int   g_pos[NN];
__device__ int   g_gcnt[NG];
__device__ int   g_bsum[SCAN_BLKS];
__device__ int   g_boff[SCAN_BLKS];
__device__ int   g_scnt;
__device__ int   g_flag;
__device__ __align__(16) int2 g_edge[NE];    // {src, float_bits(coef)}

union HPack { uint2 u; __half2 h[2]; };

// ---------------- HMMA helper ----------------------------------------------
__device__ __forceinline__ void mma16816(float* c, unsigned a0, unsigned a1,
                                         unsigned a2, unsigned a3,
                                         unsigned b0, unsigned b1) {
    asm volatile(
        "mma.sync.aligned.m16n8k16.row.col.f32.f16.f16.f32 "
        "{%0,%1,%2,%3}, {%4,%5,%6,%7}, {%8,%9}, {%0,%1,%2,%3};"
        : "+f"(c[0]), "+f"(c[1]), "+f"(c[2]), "+f"(c[3])
        : "r"(a0), "r"(a1), "r"(a2), "r"(a3), "r"(b0), "r"(b1));
}

// ---------------- init: all zeroing in one launch --------------------------
__global__ void k_init() {
    int t = blockIdx.x * 256 + threadIdx.x;
    if (t < NN) g_degi[t] = 0;
    if (t < NG) g_gcnt[t] = 0;
    if (t < NG * HID) g_pool[t] = 0.f;
    if (t == 0) { g_scnt = 0; g_flag = 0; }
}

// ---------------- gemm1 via HMMA: Y = fp16(X @ W1), W1 converted in-block --
__device__ __forceinline__ void gemm1_mma(const float* __restrict__ X,
                                          const float* __restrict__ W1,
                                          __half* __restrict__ Y, int blk) {
    const int XS = 136;
    __shared__ __align__(16) __half Xs[64 * XS];
    __shared__ __align__(16) __half Ws[64 * XS];
    int t = threadIdx.x;
    int node0 = blk * 64;
#pragma unroll
    for (int i = 0; i < 8; i++) {
        int idx = t + i * 256;
        int row = idx >> 5, c4 = idx & 31;
        int node = node0 + row;
        if (node >= NN) node = NN - 1;
        float4 v = __ldg((const float4*)&X[(size_t)node * DIN + c4 * 4]);
        HPack pk;
        pk.h[0] = __floats2half2_rn(v.x, v.y);
        pk.h[1] = __floats2half2_rn(v.z, v.w);
        *(uint2*)&Xs[row * XS + c4 * 4] = pk.u;
    }
    // W1 [k][n] fp32 -> Ws [n][k] fp16 (L2-resident after first block)
#pragma unroll
    for (int i = 0; i < 32; i++) {
        int idx = t + i * 256;
        int n = idx & 63, k = idx >> 6;
        Ws[n * XS + k] = __float2half(__ldg(&W1[k * HID + n]));
    }
    __syncthreads();

    int warp = t >> 5, lane = t & 31;
    int g = lane >> 2, tq = lane & 3;
    int mrow = (warp >> 1) * 16, ncol = (warp & 1) * 32;
    float acc[4][4];
#pragma unroll
    for (int j = 0; j < 4; j++)
#pragma unroll
        for (int c = 0; c < 4; c++) acc[j][c] = 0.f;

#pragma unroll
    for (int k0 = 0; k0 < DIN / 16; k0++) {
        int kb = k0 * 16 + 2 * tq;
        unsigned a0 = *(const unsigned*)&Xs[(mrow + g) * XS + kb];
        unsigned a1 = *(const unsigned*)&Xs[(mrow + g + 8) * XS + kb];
        unsigned a2 = *(const unsigned*)&Xs[(mrow + g) * XS + kb + 8];
        unsigned a3 = *(const unsigned*)&Xs[(mrow + g + 8) * XS + kb + 8];
#pragma unroll
        for (int j = 0; j < 4; j++) {
            int n = ncol + j * 8 + g;
            unsigned b0 = *(const unsigned*)&Ws[n * XS + kb];
            unsigned b1 = *(const unsigned*)&Ws[n * XS + kb + 8];
            mma16816(acc[j], a0, a1, a2, a3, b0, b1);
        }
    }
#pragma unroll
    for (int j = 0; j < 4; j++) {
        int col = ncol + j * 8 + 2 * tq;
        int n1 = node0 + mrow + g, n2 = n1 + 8;
        if (n1 < NN) {
            __half2 p = __floats2half2_rn(acc[j][0], acc[j][1]);
            *(__half2*)&Y[(size_t)n1 * HID + col] = p;
        }
        if (n2 < NN) {
            __half2 p = __floats2half2_rn(acc[j][2], acc[j][3]);
            *(__half2*)&Y[(size_t)n2 * HID + col] = p;
        }
    }
}

// ------- fused front: gemm1 | degree hist | graph hist | W2t prep ----------
__global__ void k_front(const float* __restrict__ x, const float* __restrict__ W1,
                        const float* __restrict__ W2,
                        const int* __restrict__ ei, const int* __restrict__ batch,
                        __half* __restrict__ Y) {
    int b = blockIdx.x;
    if (b < GEMM1_BLKS) {
        gemm1_mma(x, W1, Y, b);
    } else if (b < GEMM1_BLKS + DEG4_BLKS) {
        int q = (b - GEMM1_BLKS) * 256 + threadIdx.x;
        if (q < NE / 4) {
            int4 d4 = __ldg((const int4*)(ei + NE) + q);
            atomicAdd(&g_degi[d4.x], 1);
            atomicAdd(&g_degi[d4.y], 1);
            atomicAdd(&g_degi[d4.z], 1);
            atomicAdd(&g_degi[d4.w], 1);
        }
    } else if (b < GEMM1_BLKS + DEG4_BLKS + GCNT4_BLKS) {
        int q = (b - GEMM1_BLKS - DEG4_BLKS) * 256 + threadIdx.x;
        if (q < NN / 4) {
            int4 b4 = __ldg((const int4*)batch + q);
            atomicAdd(&g_gcnt[b4.x], 1);
            atomicAdd(&g_gcnt[b4.y], 1);
            atomicAdd(&g_gcnt[b4.z], 1);
            atomicAdd(&g_gcnt[b4.w], 1);
        }
    } else {
        int q = (b - GEMM1_BLKS - DEG4_BLKS - GCNT4_BLKS) * 256 + threadIdx.x;
        if (q < HID * HID) {
            int k = q >> 6, n = q & 63;
            g_W2t[n * HID + k] = __float2half(W2[q]);
        }
    }
}

// ---------------- single-kernel scan (98 resident blocks, flag sync) -------
__global__ void k_scan() {
    __shared__ int wsum[32];
    __shared__ int amLast;
    __shared__ int ws2[4];
    int b = blockIdx.x, t = threadIdx.x;
    int lane = t & 31, w = t >> 5;
    int idx = b * 1024 + t;
    int d = (idx < NN) ? g_degi[idx] : 0;

    // local inclusive scan: warp shfl scan + warp-sum scan
    int v = d;
#pragma unroll
    for (int o = 1; o < 32; o <<= 1) {
        int u = __shfl_up_sync(0xffffffffu, v, o);
        if (lane >= o) v += u;
    }
    if (lane == 31) wsum[w] = v;
    __syncthreads();
    if (w == 0) {
        int s = wsum[lane];
#pragma unroll
        for (int o = 1; o < 32; o <<= 1) {
            int u = __shfl_up_sync(0xffffffffu, s, o);
            if (lane >= o) s += u;
        }
        wsum[lane] = s;
    }
    __syncthreads();
    int incl = v + (w > 0 ? wsum[w - 1] : 0);
    int total = wsum[31];

    // publish block total; detect last arrival
    if (t == 0) {
        g_bsum[b] = total;
        __threadfence();
        int c = atomicAdd(&g_scnt, 1);
        amLast = (c == SCAN_BLKS - 1);
    }
    __syncthreads();

    if (amLast) {
        if (t < 128) {
            int orig = (t < SCAN_BLKS) ? ((volatile int*)g_bsum)[t] : 0;
            int v2 = orig;
#pragma unroll
            for (int o = 1; o < 32; o <<= 1) {
                int u = __shfl_up_sync(0xffffffffu, v2, o);
                if (lane >= o) v2 += u;
            }
            if (lane == 31) ws2[w] = v2;
            asm volatile("bar.sync 1, 128;" ::: "memory");
            int add = 0;
#pragma unroll
            for (int k = 0; k < 4; k++) add += (k < w) ? ws2[k] : 0;
            if (t < SCAN_BLKS) g_boff[t] = v2 + add - orig;
        }
        __syncthreads();
        if (t == 0) { __threadfence(); atomicExch(&g_flag, 1); }
    }

    // wait for offsets
    if (t == 0) { while (atomicAdd(&g_flag, 0) == 0) { } }
    __syncthreads();
    int off = ((volatile int*)g_boff)[b];

    if (idx < NN) {
        int excl = incl - d + off;
        g_ptr[idx] = excl;
        g_pos[idx] = excl;
        g_dinv[idx] = rsqrtf((float)d + 1.0f);
    }
    if (b == SCAN_BLKS - 1 && t == 0) g_ptr[NN] = NE;
}

// ---------------- scatter: 2 edges per thread ------------------------------
__global__ void k_scatter(const int* __restrict__ ei) {
    int q = blockIdx.x * blockDim.x + threadIdx.x;
    if (q >= NE / 2) return;
    int2 s2 = __ldg((const int2*)ei + q);
    int2 d2 = __ldg((const int2*)(ei + NE) + q);
    int p0 = atomicAdd(&g_pos[d2.x], 1);
    int p1 = atomicAdd(&g_pos[d2.y], 1);
    float c0 = __ldg(&g_dinv[s2.x]) * __ldg(&g_dinv[d2.x]);
    float c1 = __ldg(&g_dinv[s2.y]) * __ldg(&g_dinv[d2.y]);
    g_edge[p0] = make_int2(s2.x, __float_as_int(c0));
    g_edge[p1] = make_int2(s2.y, __float_as_int(c1));
}

// ---------------- node aggregation core (branch-free MLP-8) ----------------
// Masked batches: out-of-range slots read edge {0, coef=0} — dummy gathers
// hit node 0's L2-hot line and add 0. No serial remainder path.
__device__ __forceinline__ float4 agg_node(const __half* __restrict__ H,
                                           int node, int j, int sub,
                                           const float* __restrict__ bias) {
    int start = __ldg(&g_ptr[node]);
    int end   = __ldg(&g_ptr[node + 1]);
    const uint2* h2 = (const uint2*)H;
    float4 a0 = make_float4(0.f, 0.f, 0.f, 0.f);
    float4 a1 = make_float4(0.f, 0.f, 0.f, 0.f);
    for (int p = start + sub; p < end; p += 16) {
        int2 e[8];
        HPack v[8];
#pragma unroll
        for (int u = 0; u < 8; u++) {
            int q = p + 2 * u;
            e[u] = (q < end) ? __ldg(&g_edge[q]) : make_int2(0, 0);
        }
#pragma unroll
        for (int u = 0; u < 8; u++) v[u].u = __ldg(h2 + (size_t)e[u].x * 16 + j);
#pragma unroll
        for (int u = 0; u < 8; u++) {
            float c = __int_as_float(e[u].y);
            float2 fa = __half22float2(v[u].h[0]), fb = __half22float2(v[u].h[1]);
            if (u & 1) {
                a1.x += fa.x * c; a1.y += fa.y * c; a1.z += fb.x * c; a1.w += fb.y * c;
            } else {
                a0.x += fa.x * c; a0.y += fa.y * c; a0.z += fb.x * c; a0.w += fb.y * c;
            }
        }
    }
    a0.x += a1.x; a0.y += a1.y; a0.z += a1.z; a0.w += a1.w;
    a0.x += __shfl_down_sync(0xffffffffu, a0.x, 16);
    a0.y += __shfl_down_sync(0xffffffffu, a0.y, 16);
    a0.z += __shfl_down_sync(0xffffffffu, a0.z, 16);
    a0.w += __shfl_down_sync(0xffffffffu, a0.w, 16);
    float4 r = make_float4(0.f, 0.f, 0.f, 0.f);
    if (sub == 0) {
        float dn = __ldg(&g_dinv[node]);
        float c = dn * dn;
        HPack hs;
        hs.u = __ldg((const uint2*)H + (size_t)node * 16 + j);
        float2 ha = __half22float2(hs.h[0]), hb = __half22float2(hs.h[1]);
        float4 b = __ldg((const float4*)bias + j);
        r.x = fmaxf(a0.x + ha.x * c + b.x, 0.f);
        r.y = fmaxf(a0.y + ha.y * c + b.y, 0.f);
        r.z = fmaxf(a0.z + hb.x * c + b.z, 0.f);
        r.w = fmaxf(a0.w + hb.y * c + b.w, 0.f);
    }
    return r;
}

// ---------------- fused agg1 + gemm2(HMMA): reads g_h, writes g_h2 ---------
__global__ void k_mid(const float* __restrict__ bias, __half* __restrict__ Y) {
    const int AS = 72;
    __shared__ __align__(16) __half As[64 * AS];
    __shared__ __align__(16) __half W2s[64 * AS];
    int t = threadIdx.x;
    int warp = t >> 5, lane = t & 31;
    int j = lane & 15, sub = lane >> 4;
    int node0 = blockIdx.x * 64;

#pragma unroll
    for (int i = 0; i < 2; i++) {
        int idx = t + i * 256;
        int row = idx >> 3, c = idx & 7;
        ((float4*)W2s)[row * 9 + c] = ((const float4*)g_W2t)[row * 8 + c];
    }

#pragma unroll 1
    for (int s = 0; s < 8; s++) {
        int row = warp * 8 + s;
        int node = node0 + row;
        float4 r = make_float4(0.f, 0.f, 0.f, 0.f);
        if (node < NN) r = agg_node(g_h, node, j, sub, bias);
        if (sub == 0) {
            HPack pk;
            pk.h[0] = __floats2half2_rn(r.x, r.y);
            pk.h[1] = __floats2half2_rn(r.z, r.w);
            *(uint2*)&As[row * AS + 4 * j] = pk.u;
        }
    }
    __syncthreads();

    int g = lane >> 2, tq = lane & 3;
    int mrow = (warp >> 1) * 16, ncol = (warp & 1) * 32;
    float acc[4][4];
#pragma unroll
    for (int jj = 0; jj < 4; jj++)
#pragma unroll
        for (int c = 0; c < 4; c++) acc[jj][c] = 0.f;

#pragma unroll
    for (int k0 = 0; k0 < HID / 16; k0++) {
        int kb = k0 * 16 + 2 * tq;
        unsigned a0 = *(const unsigned*)&As[(mrow + g) * AS + kb];
        unsigned a1 = *(const unsigned*)&As[(mrow + g + 8) * AS + kb];
        unsigned a2 = *(const unsigned*)&As[(mrow + g) * AS + kb + 8];
        unsigned a3 = *(const unsigned*)&As[(mrow + g + 8) * AS + kb + 8];
#pragma unroll
        for (int jj = 0; jj < 4; jj++) {
            int n = ncol + jj * 8 + g;
            unsigned b0 = *(const unsigned*)&W2s[n * AS + kb];
            unsigned b1 = *(const unsigned*)&W2s[n * AS + kb + 8];
            mma16816(acc[jj], a0, a1, a2, a3, b0, b1);
        }
    }
#pragma unroll
    for (int jj = 0; jj < 4; jj++) {
        int col = ncol + jj * 8 + 2 * tq;
        int n1 = node0 + mrow + g, n2 = n1 + 8;
        if (n1 < NN) {
            __half2 p = __floats2half2_rn(acc[jj][0], acc[jj][1]);
            *(__half2*)&Y[(size_t)n1 * HID + col] = p;
        }
        if (n2 < NN) {
            __half2 p = __floats2half2_rn(acc[jj][2], acc[jj][3]);
            *(__half2*)&Y[(size_t)n2 * HID + col] = p;
        }
    }
}

// ---------------- layer-2 aggregation + fused pool (reads g_h2) ------------
__global__ void k_aggpool(const float* __restrict__ bias,
                          const int* __restrict__ batch) {
    int warp = threadIdx.x >> 5, lane = threadIdx.x & 31;
    int j = lane & 15, sub = lane >> 4;
    int node = blockIdx.x * 8 + warp;
    if (node >= NN) return;
    float4 r = agg_node(g_h2, node, j, sub, bias);
    if (sub == 0) {
        int g = __ldg(&batch[node]);
        float4* p4 = (float4*)g_pool + (size_t)g * 16 + j;
        asm volatile("red.global.add.v4.f32 [%0], {%1, %2, %3, %4};"
                     :: "l"(p4), "f"(r.x), "f"(r.y), "f"(r.z), "f"(r.w)
                     : "memory");
    }
}

// ---------------- head -----------------------------------------------------
__global__ void k_head(const float* __restrict__ Wfc, const float* __restrict__ bfc,
                       float* __restrict__ out) {
    __shared__ float Wf[HID * NC];
    __shared__ float bf[NC];
    for (int i = threadIdx.x; i < HID * NC; i += blockDim.x) Wf[i] = Wfc[i];
    if (threadIdx.x < NC) bf[threadIdx.x] = bfc[threadIdx.x];
    __syncthreads();
    int g = blockIdx.x * blockDim.x + threadIdx.x;
    if (g >= NG) return;
    float inv = 1.0f / fmaxf((float)g_gcnt[g], 1.0f);
    float l[NC];
#pragma unroll
    for (int j = 0; j < NC; j++) l[j] = bf[j];
    for (int k = 0; k < HID; k++) {
        float pv = g_pool[g * HID + k] * inv;
#pragma unroll
        for (int j = 0; j < NC; j++) l[j] += pv * Wf[k * NC + j];
    }
    float m = l[0];
#pragma unroll
    for (int j = 1; j < NC; j++) m = fmaxf(m, l[j]);
    float s = 0.f;
#pragma unroll
    for (int j = 0; j < NC; j++) s += expf(l[j] - m);
    float lse = m + logf(s);
#pragma unroll
    for (int j = 0; j < NC; j++) out[g * NC + j] = l[j] - lse;
}

// ---------------------------------------------------------------------------
extern "C" void kernel_launch(void* const* d_in, const int* in_sizes, int n_in,
                              void* d_out, int out_size) {
    const float* x     = (const float*)d_in[0];
    const int*   ei    = (const int*)d_in[1];
    const int*   batch = (const int*)d_in[2];
    const float* W1    = (const float*)d_in[3];
    const float* b1    = (const float*)d_in[4];
    const float* W2    = (const float*)d_in[5];
    const float* b2    = (const float*)d_in[6];
    const float* Wfc   = (const float*)d_in[7];
    const float* bfc   = (const float*)d_in[8];
    float* out = (float*)d_out;

    // Resolve REAL device addresses (host shadow symbols are a silent ATS trap).
    void *p_h, *p_h2;
    cudaGetSymbolAddress(&p_h,  g_h);
    cudaGetSymbolAddress(&p_h2, g_h2);
    __half* dh  = (__half*)p_h;
    __half* dh2 = (__half*)p_h2;

    // all zeroing in one kernel
    k_init<<<(NN + 255) / 256, 256>>>();

    // fused: gemm1(HMMA, in-block W1 convert) + histograms + W2t prep
    k_front<<<GEMM1_BLKS + DEG4_BLKS + GCNT4_BLKS + W2_BLKS, 256>>>(
        x, W1, W2, ei, batch, dh);

    // single-kernel CSR pointer scan
    k_scan<<<SCAN_BLKS, 1024>>>();

    // packed edge scatter (2 edges/thread)
    k_scatter<<<(NE / 2 + 255) / 256, 256>>>(ei);

    // fused agg1 + gemm2(HMMA): reads g_h, writes g_h2
    k_mid<<<(NN + 63) / 64, 256>>>(b1, dh2);

    // layer-2 aggregation + fused pool (reads g_h2)
    k_aggpool<<<(NN + 7) / 8, 256>>>(b2, batch);

    // head
    k_head<<<1, NG>>>(Wfc, bfc, out);
}

// round 14
// speedup vs baseline: 1.3267x; 1.0091x over previous
#include <cuda_runtime.h>
#include <cuda_fp16.h>

#define NN 100000
#define NE 1600000
#define DIN 128
#define HID 64
#define NG 512
#define NC 10

#define GEMM1_BLKS ((NN + 63) / 64)          // 1563
#define DEG4_BLKS  ((NE / 4 + 255) / 256)    // 1563
#define GCNT4_BLKS ((NN / 4 + 255) / 256)    // 98
#define SCAN_BLKS  ((NN + 1023) / 1024)      // 98

// ---------------- scratch (device globals; no allocation allowed) ----------
__device__ __align__(16) __half g_h[NN * HID];    // layer-1 features
__device__ __align__(16) __half g_h2[NN * HID];   // layer-2 features
__device__ __align__(16) __half g_W1t[HID * DIN]; // W1^T fp16 [n][k]
__device__ __align__(16) __half g_W2t[HID * HID]; // W2^T fp16 [n][k]
__device__ __align__(16) float g_pool[NG * HID];
__device__ float g_dinv[NN];
__device__ int   g_degi[NN];
__device__ int   g_ptr[NN + 1];
__device__ int   g_pos[NN];
__device__ int   g_gcnt[NG];
__device__ int   g_bsum[SCAN_BLKS];
__device__ int   g_boff[SCAN_BLKS];
__device__ int   g_scnt;
__device__ int   g_flag;
__device__ __align__(16) int2 g_edge[NE];    // {src, float_bits(coef)}

union HPack { uint2 u; __half2 h[2]; };

// ---------------- HMMA helper ----------------------------------------------
__device__ __forceinline__ void mma16816(float* c, unsigned a0, unsigned a1,
                                         unsigned a2, unsigned a3,
                                         unsigned b0, unsigned b1) {
    asm volatile(
        "mma.sync.aligned.m16n8k16.row.col.f32.f16.f16.f32 "
        "{%0,%1,%2,%3}, {%4,%5,%6,%7}, {%8,%9}, {%0,%1,%2,%3};"
        : "+f"(c[0]), "+f"(c[1]), "+f"(c[2]), "+f"(c[3])
        : "r"(a0), "r"(a1), "r"(a2), "r"(a3), "r"(b0), "r"(b1));
}

// ---------------- init: zeroing + weight transpose/convert -----------------
__global__ void k_init(const float* __restrict__ W1, const float* __restrict__ W2) {
    int t = blockIdx.x * 256 + threadIdx.x;
    if (t < NN) g_degi[t] = 0;
    if (t < NG) g_gcnt[t] = 0;
    if (t < NG * HID) g_pool[t] = 0.f;
    if (t == 0) { g_scnt = 0; g_flag = 0; }
    if (t < DIN * HID) {
        int k = t >> 6, n = t & 63;
        g_W1t[n * DIN + k] = __float2half(W1[t]);
    } else if (t < DIN * HID + HID * HID) {
        int q = t - DIN * HID;
        int k = q >> 6, n = q & 63;
        g_W2t[n * HID + k] = __float2half(W2[q]);
    }
}

// ---------------- gemm1 via HMMA: Y = fp16(X @ W1) -------------------------
__device__ __forceinline__ void gemm1_mma(const float* __restrict__ X,
                                          __half* __restrict__ Y, int blk) {
    const int XS = 136;
    __shared__ __align__(16) __half Xs[64 * XS];
    __shared__ __align__(16) __half Ws[64 * XS];
    int t = threadIdx.x;
    int node0 = blk * 64;
#pragma unroll
    for (int i = 0; i < 8; i++) {
        int idx = t + i * 256;
        int row = idx >> 5, c4 = idx & 31;
        int node = node0 + row;
        if (node >= NN) node = NN - 1;
        float4 v = __ldg((const float4*)&X[(size_t)node * DIN + c4 * 4]);
        HPack pk;
        pk.h[0] = __floats2half2_rn(v.x, v.y);
        pk.h[1] = __floats2half2_rn(v.z, v.w);
        *(uint2*)&Xs[row * XS + c4 * 4] = pk.u;
    }
#pragma unroll
    for (int i = 0; i < 4; i++) {
        int idx = t + i * 256;
        int row = idx >> 4, c = idx & 15;
        ((float4*)Ws)[row * 17 + c] = ((const float4*)g_W1t)[row * 16 + c];
    }
    __syncthreads();

    int warp = t >> 5, lane = t & 31;
    int g = lane >> 2, tq = lane & 3;
    int mrow = (warp >> 1) * 16, ncol = (warp & 1) * 32;
    float acc[4][4];
#pragma unroll
    for (int j = 0; j < 4; j++)
#pragma unroll
        for (int c = 0; c < 4; c++) acc[j][c] = 0.f;

#pragma unroll
    for (int k0 = 0; k0 < DIN / 16; k0++) {
        int kb = k0 * 16 + 2 * tq;
        unsigned a0 = *(const unsigned*)&Xs[(mrow + g) * XS + kb];
        unsigned a1 = *(const unsigned*)&Xs[(mrow + g + 8) * XS + kb];
        unsigned a2 = *(const unsigned*)&Xs[(mrow + g) * XS + kb + 8];
        unsigned a3 = *(const unsigned*)&Xs[(mrow + g + 8) * XS + kb + 8];
#pragma unroll
        for (int j = 0; j < 4; j++) {
            int n = ncol + j * 8 + g;
            unsigned b0 = *(const unsigned*)&Ws[n * XS + kb];
            unsigned b1 = *(const unsigned*)&Ws[n * XS + kb + 8];
            mma16816(acc[j], a0, a1, a2, a3, b0, b1);
        }
    }
#pragma unroll
    for (int j = 0; j < 4; j++) {
        int col = ncol + j * 8 + 2 * tq;
        int n1 = node0 + mrow + g, n2 = n1 + 8;
        if (n1 < NN) {
            __half2 p = __floats2half2_rn(acc[j][0], acc[j][1]);
            *(__half2*)&Y[(size_t)n1 * HID + col] = p;
        }
        if (n2 < NN) {
            __half2 p = __floats2half2_rn(acc[j][2], acc[j][3]);
            *(__half2*)&Y[(size_t)n2 * HID + col] = p;
        }
    }
}

// ------- fused front: gemm1 | degree hist | graph hist ---------------------
__global__ void k_front(const float* __restrict__ x,
                        const int* __restrict__ ei, const int* __restrict__ batch,
                        __half* __restrict__ Y) {
    int b = blockIdx.x;
    if (b < GEMM1_BLKS) {
        gemm1_mma(x, Y, b);
    } else if (b < GEMM1_BLKS + DEG4_BLKS) {
        int q = (b - GEMM1_BLKS) * 256 + threadIdx.x;
        if (q < NE / 4) {
            int4 d4 = __ldg((const int4*)(ei + NE) + q);
            atomicAdd(&g_degi[d4.x], 1);
            atomicAdd(&g_degi[d4.y], 1);
            atomicAdd(&g_degi[d4.z], 1);
            atomicAdd(&g_degi[d4.w], 1);
        }
    } else {
        int q = (b - GEMM1_BLKS - DEG4_BLKS) * 256 + threadIdx.x;
        if (q < NN / 4) {
            int4 b4 = __ldg((const int4*)batch + q);
            atomicAdd(&g_gcnt[b4.x], 1);
            atomicAdd(&g_gcnt[b4.y], 1);
            atomicAdd(&g_gcnt[b4.z], 1);
            atomicAdd(&g_gcnt[b4.w], 1);
        }
    }
}

// ---------------- single-kernel scan (98 resident blocks, flag sync) -------
__global__ void k_scan() {
    __shared__ int wsum[32];
    __shared__ int amLast;
    __shared__ int ws2[4];
    int b = blockIdx.x, t = threadIdx.x;
    int lane = t & 31, w = t >> 5;
    int idx = b * 1024 + t;
    int d = (idx < NN) ? g_degi[idx] : 0;

    int v = d;
#pragma unroll
    for (int o = 1; o < 32; o <<= 1) {
        int u = __shfl_up_sync(0xffffffffu, v, o);
        if (lane >= o) v += u;
    }
    if (lane == 31) wsum[w] = v;
    __syncthreads();
    if (w == 0) {
        int s = wsum[lane];
#pragma unroll
        for (int o = 1; o < 32; o <<= 1) {
            int u = __shfl_up_sync(0xffffffffu, s, o);
            if (lane >= o) s += u;
        }
        wsum[lane] = s;
    }
    __syncthreads();
    int incl = v + (w > 0 ? wsum[w - 1] : 0);
    int total = wsum[31];

    if (t == 0) {
        g_bsum[b] = total;
        __threadfence();
        int c = atomicAdd(&g_scnt, 1);
        amLast = (c == SCAN_BLKS - 1);
    }
    __syncthreads();

    if (amLast) {
        if (t < 128) {
            int orig = (t < SCAN_BLKS) ? ((volatile int*)g_bsum)[t] : 0;
            int v2 = orig;
#pragma unroll
            for (int o = 1; o < 32; o <<= 1) {
                int u = __shfl_up_sync(0xffffffffu, v2, o);
                if (lane >= o) v2 += u;
            }
            if (lane == 31) ws2[w] = v2;
            asm volatile("bar.sync 1, 128;" ::: "memory");
            int add = 0;
#pragma unroll
            for (int k = 0; k < 4; k++) add += (k < w) ? ws2[k] : 0;
            if (t < SCAN_BLKS) g_boff[t] = v2 + add - orig;
        }
        __syncthreads();
        if (t == 0) { __threadfence(); atomicExch(&g_flag, 1); }
    }

    if (t == 0) { while (atomicAdd(&g_flag, 0) == 0) { } }
    __syncthreads();
    int off = ((volatile int*)g_boff)[b];

    if (idx < NN) {
        int excl = incl - d + off;
        g_ptr[idx] = excl;
        g_pos[idx] = excl;
        g_dinv[idx] = rsqrtf((float)d + 1.0f);
    }
    if (b == SCAN_BLKS - 1 && t == 0) g_ptr[NN] = NE;
}

// ---------------- scatter: 4 edges per thread (4 atomic chains in flight) --
__global__ void k_scatter(const int* __restrict__ ei) {
    int q = blockIdx.x * blockDim.x + threadIdx.x;
    if (q >= NE / 4) return;
    int4 s4 = __ldg((const int4*)ei + q);
    int4 d4 = __ldg((const int4*)(ei + NE) + q);
    int p0 = atomicAdd(&g_pos[d4.x], 1);
    int p1 = atomicAdd(&g_pos[d4.y], 1);
    int p2 = atomicAdd(&g_pos[d4.z], 1);
    int p3 = atomicAdd(&g_pos[d4.w], 1);
    float c0 = __ldg(&g_dinv[s4.x]) * __ldg(&g_dinv[d4.x]);
    float c1 = __ldg(&g_dinv[s4.y]) * __ldg(&g_dinv[d4.y]);
    float c2 = __ldg(&g_dinv[s4.z]) * __ldg(&g_dinv[d4.z]);
    float c3 = __ldg(&g_dinv[s4.w]) * __ldg(&g_dinv[d4.w]);
    g_edge[p0] = make_int2(s4.x, __float_as_int(c0));
    g_edge[p1] = make_int2(s4.y, __float_as_int(c1));
    g_edge[p2] = make_int2(s4.z, __float_as_int(c2));
    g_edge[p3] = make_int2(s4.w, __float_as_int(c3));
}

// ---------------- node aggregation core (branch-free MLP-8) ----------------
__device__ __forceinline__ float4 agg_node(const __half* __restrict__ H,
                                           int node, int j, int sub,
                                           const float* __restrict__ bias) {
    int start = __ldg(&g_ptr[node]);
    int end   = __ldg(&g_ptr[node + 1]);
    const uint2* h2 = (const uint2*)H;
    float4 a0 = make_float4(0.f, 0.f, 0.f, 0.f);
    float4 a1 = make_float4(0.f, 0.f, 0.f, 0.f);
    for (int p = start + sub; p < end; p += 16) {
        int2 e[8];
        HPack v[8];
#pragma unroll
        for (int u = 0; u < 8; u++) {
            int q = p + 2 * u;
            e[u] = (q < end) ? __ldg(&g_edge[q]) : make_int2(0, 0);
        }
#pragma unroll
        for (int u = 0; u < 8; u++) v[u].u = __ldg(h2 + (size_t)e[u].x * 16 + j);
#pragma unroll
        for (int u = 0; u < 8; u++) {
            float c = __int_as_float(e[u].y);
            float2 fa = __half22float2(v[u].h[0]), fb = __half22float2(v[u].h[1]);
            if (u & 1) {
                a1.x += fa.x * c; a1.y += fa.y * c; a1.z += fb.x * c; a1.w += fb.y * c;
            } else {
                a0.x += fa.x * c; a0.y += fa.y * c; a0.z += fb.x * c; a0.w += fb.y * c;
            }
        }
    }
    a0.x += a1.x; a0.y += a1.y; a0.z += a1.z; a0.w += a1.w;
    a0.x += __shfl_down_sync(0xffffffffu, a0.x, 16);
    a0.y += __shfl_down_sync(0xffffffffu, a0.y, 16);
    a0.z += __shfl_down_sync(0xffffffffu, a0.z, 16);
    a0.w += __shfl_down_sync(0xffffffffu, a0.w, 16);
    float4 r = make_float4(0.f, 0.f, 0.f, 0.f);
    if (sub == 0) {
        float dn = __ldg(&g_dinv[node]);
        float c = dn * dn;
        HPack hs;
        hs.u = __ldg((const uint2*)H + (size_t)node * 16 + j);
        float2 ha = __half22float2(hs.h[0]), hb = __half22float2(hs.h[1]);
        float4 b = __ldg((const float4*)bias + j);
        r.x = fmaxf(a0.x + ha.x * c + b.x, 0.f);
        r.y = fmaxf(a0.y + ha.y * c + b.y, 0.f);
        r.z = fmaxf(a0.z + hb.x * c + b.z, 0.f);
        r.w = fmaxf(a0.w + hb.y * c + b.w, 0.f);
    }
    return r;
}

// ---------------- fused agg1 + gemm2(HMMA): reads g_h, writes g_h2 ---------
__global__ void k_mid(const float* __restrict__ bias, __half* __restrict__ Y) {
    const int AS = 72;
    __shared__ __align__(16) __half As[64 * AS];
    __shared__ __align__(16) __half W2s[64 * AS];
    int t = threadIdx.x;
    int warp = t >> 5, lane = t & 31;
    int j = lane & 15, sub = lane >> 4;
    int node0 = blockIdx.x * 64;

#pragma unroll
    for (int i = 0; i < 2; i++) {
        int idx = t + i * 256;
        int row = idx >> 3, c = idx & 7;
        ((float4*)W2s)[row * 9 + c] = ((const float4*)g_W2t)[row * 8 + c];
    }

#pragma unroll 1
    for (int s = 0; s < 8; s++) {
        int row = warp * 8 + s;
        int node = node0 + row;
        float4 r = make_float4(0.f, 0.f, 0.f, 0.f);
        if (node < NN) r = agg_node(g_h, node, j, sub, bias);
        if (sub == 0) {
            HPack pk;
            pk.h[0] = __floats2half2_rn(r.x, r.y);
            pk.h[1] = __floats2half2_rn(r.z, r.w);
            *(uint2*)&As[row * AS + 4 * j] = pk.u;
        }
    }
    __syncthreads();

    int g = lane >> 2, tq = lane & 3;
    int mrow = (warp >> 1) * 16, ncol = (warp & 1) * 32;
    float acc[4][4];
#pragma unroll
    for (int jj = 0; jj < 4; jj++)
#pragma unroll
        for (int c = 0; c < 4; c++) acc[jj][c] = 0.f;

#pragma unroll
    for (int k0 = 0; k0 < HID / 16; k0++) {
        int kb = k0 * 16 + 2 * tq;
        unsigned a0 = *(const unsigned*)&As[(mrow + g) * AS + kb];
        unsigned a1 = *(const unsigned*)&As[(mrow + g + 8) * AS + kb];
        unsigned a2 = *(const unsigned*)&As[(mrow + g) * AS + kb + 8];
        unsigned a3 = *(const unsigned*)&As[(mrow + g + 8) * AS + kb + 8];
#pragma unroll
        for (int jj = 0; jj < 4; jj++) {
            int n = ncol + jj * 8 + g;
            unsigned b0 = *(const unsigned*)&W2s[n * AS + kb];
            unsigned b1 = *(const unsigned*)&W2s[n * AS + kb + 8];
            mma16816(acc[jj], a0, a1, a2, a3, b0, b1);
        }
    }
#pragma unroll
    for (int jj = 0; jj < 4; jj++) {
        int col = ncol + jj * 8 + 2 * tq;
        int n1 = node0 + mrow + g, n2 = n1 + 8;
        if (n1 < NN) {
            __half2 p = __floats2half2_rn(acc[jj][0], acc[jj][1]);
            *(__half2*)&Y[(size_t)n1 * HID + col] = p;
        }
        if (n2 < NN) {
            __half2 p = __floats2half2_rn(acc[jj][2], acc[jj][3]);
            *(__half2*)&Y[(size_t)n2 * HID + col] = p;
        }
    }
}

// ---------------- layer-2 aggregation + fused pool (reads g_h2) ------------
__global__ void k_aggpool(const float* __restrict__ bias,
                          const int* __restrict__ batch) {
    int warp = threadIdx.x >> 5, lane = threadIdx.x & 31;
    int j = lane & 15, sub = lane >> 4;
    int node = blockIdx.x * 8 + warp;
    if (node >= NN) return;
    float4 r = agg_node(g_h2, node, j, sub, bias);
    if (sub == 0) {
        int g = __ldg(&batch[node]);
        float4* p4 = (float4*)g_pool + (size_t)g * 16 + j;
        asm volatile("red.global.add.v4.f32 [%0], {%1, %2, %3, %4};"
                     :: "l"(p4), "f"(r.x), "f"(r.y), "f"(r.z), "f"(r.w)
                     : "memory");
    }
}

// ---------------- head -----------------------------------------------------
__global__ void k_head(const float* __restrict__ Wfc, const float* __restrict__ bfc,
                       float* __restrict__ out) {
    __shared__ float Wf[HID * NC];
    __shared__ float bf[NC];
    for (int i = threadIdx.x; i < HID * NC; i += blockDim.x) Wf[i] = Wfc[i];
    if (threadIdx.x < NC) bf[threadIdx.x] = bfc[threadIdx.x];
    __syncthreads();
    int g = blockIdx.x * blockDim.x + threadIdx.x;
    if (g >= NG) return;
    float inv = 1.0f / fmaxf((float)g_gcnt[g], 1.0f);
    float l[NC];
#pragma unroll
    for (int j = 0; j < NC; j++) l[j] = bf[j];
    for (int k = 0; k < HID; k++) {
        float pv = g_pool[g * HID + k] * inv;
#pragma unroll
        for (int j = 0; j < NC; j++) l[j] += pv * Wf[k * NC + j];
    }
    float m = l[0];
#pragma unroll
    for (int j = 1; j < NC; j++) m = fmaxf(m, l[j]);
    float s = 0.f;
#pragma unroll
    for (int j = 0; j < NC; j++) s += expf(l[j] - m);
    float lse = m + logf(s);
#pragma unroll
    for (int j = 0; j < NC; j++) out[g * NC + j] = l[j] - lse;
}

// ---------------------------------------------------------------------------
extern "C" void kernel_launch(void* const* d_in, const int* in_sizes, int n_in,
                              void* d_out, int out_size) {
    const float* x     = (const float*)d_in[0];
    const int*   ei    = (const int*)d_in[1];
    const int*   batch = (const int*)d_in[2];
    const float* W1    = (const float*)d_in[3];
    const float* b1    = (const float*)d_in[4];
    const float* W2    = (const float*)d_in[5];
    const float* b2    = (const float*)d_in[6];
    const float* Wfc   = (const float*)d_in[7];
    const float* bfc   = (const float*)d_in[8];
    float* out = (float*)d_out;

    // Resolve REAL device addresses (host shadow symbols are a silent ATS trap).
    void *p_h, *p_h2;
    cudaGetSymbolAddress(&p_h,  g_h);
    cudaGetSymbolAddress(&p_h2, g_h2);
    __half* dh  = (__half*)p_h;
    __half* dh2 = (__half*)p_h2;

    // zeroing + weight transpose/convert in one kernel
    k_init<<<(NN + 255) / 256, 256>>>(W1, W2);

    // fused: gemm1(HMMA) + degree histogram + graph histogram
    k_front<<<GEMM1_BLKS + DEG4_BLKS + GCNT4_BLKS, 256>>>(x, ei, batch, dh);

    // single-kernel CSR pointer scan
    k_scan<<<SCAN_BLKS, 1024>>>();

    // packed edge scatter (4 edges/thread)
    k_scatter<<<(NE / 4 + 255) / 256, 256>>>(ei);

    // fused agg1 + gemm2(HMMA): reads g_h, writes g_h2
    k_mid<<<(NN + 63) / 64, 256>>>(b1, dh2);

    // layer-2 aggregation + fused pool (reads g_h2)
    k_aggpool<<<(NN + 7) / 8, 256>>>(b2, batch);

    // head
    k_head<<<1, NG>>>(Wfc, bfc, out);
}